// round 7
// baseline (speedup 1.0000x reference)
#include <cuda_runtime.h>
#include <cuda_bf16.h>

// Problem constants
#define PB    32    // batch
#define NN    8     // objects
#define P0    64
#define P1    128
#define P2    64
#define CC    128   // channels
#define KK    56    // permutations of (8,2)
#define NT    1024  // threads per block (8 groups x 128 channels)
#define GRID  145   // 112 binary + 32 unary + 1 nullary (single wave on 148 SMs)

// Dynamic smem: [0, 128KB) tq table (float2 per (f,c)), [128KB, 136KB) xs
#define TQ_BYTES   (128 * CC * 8)
#define SMEM_BYTES (TQ_BYTES + 2048 * 4)

// Scratch (allocation-free: __device__ globals)
__device__ float g_N0[PB * CC];
__device__ float g_U0[PB * NN * CC];
__device__ float g_U1[PB * NN * CC];
__device__ float g_B0[PB * KK * CC];
__device__ float g_B1[PB * KK * CC];
__device__ int   g_arrive;   // zero-init; self-reset each launch
__device__ int   g_done;

// tanh(x) = 1 - 2/(exp(2x)+1). Safe at large |x|.
__device__ __forceinline__ float fast_tanh(float x) {
    const float e = __expf(2.0f * x);
    return 1.0f - __fdividef(2.0f, e + 1.0f);
}

extern __shared__ __align__(16) unsigned char s_raw[];

__global__ __launch_bounds__(NT) void fused_k(const float* __restrict__ nullary,
                                              const float* __restrict__ unary,
                                              const float* __restrict__ binary,
                                              const float* __restrict__ kern,
                                              float* __restrict__ out) {
    float2* tq  = reinterpret_cast<float2*>(s_raw);            // (t, 1-t^2) per (f, c)
    float*  xs  = reinterpret_cast<float*>(s_raw + TQ_BYTES);  // x staging (2048 floats)
    const float2* xs2 = reinterpret_cast<const float2*>(xs);

    const int blk = blockIdx.x;
    const int tid = threadIdx.x;
    const int g   = tid >> 7;     // group 0..7
    const int c   = tid & 127;    // channel

    // ================= Phase 1: slot-partial mins =================
    if (blk < 112) {
        // ---- binary slots: one pair m, 32 batches x 64 features; 4 accs/thread ----
        const bool slot1 = (blk >= 56);
        const int  m     = slot1 ? blk - 56 : blk;
        const int  i     = m / 7;
        const int  jp    = m % 7;
        const int  tbase = slot1 ? 384 : 320;
        const int  bg    = g * 4;

        #pragma unroll
        for (int it = 0; it < (PB * P2) / NT; it++) {
            const int idx = it * NT + tid;
            const int b = idx >> 6, f = idx & 63;
            xs[idx] = binary[((b * NN + i) * (NN - 1) + jp) * P2 + f];
        }
        #pragma unroll
        for (int it = 0; it < (P2 * CC) / NT; it++) {
            const int idx = it * NT + tid;
            const float t = fast_tanh(kern[(tbase + (idx >> 7)) * CC + (idx & 127)]);
            tq[idx] = make_float2(t, fmaf(-t, t, 1.0f));
        }
        __syncthreads();

        float acc[4];
        #pragma unroll
        for (int b = 0; b < 4; b++) acc[b] = 1e30f;

        #pragma unroll
        for (int f2 = 0; f2 < P2 / 2; f2++) {
            const float2 ta = tq[(2 * f2) * CC + c];
            const float2 tb = tq[(2 * f2 + 1) * CC + c];
            #pragma unroll
            for (int b = 0; b < 4; b++) {
                const float2 x2 = xs2[(bg + b) * 32 + f2];
                acc[b] = fminf(acc[b], fmaf(x2.x, ta.x, ta.y));
                acc[b] = fminf(acc[b], fmaf(x2.y, tb.x, tb.y));
            }
        }

        float* dst = slot1 ? g_B1 : g_B0;
        #pragma unroll
        for (int b = 0; b < 4; b++)
            dst[((bg + b) * KK + m) * CC + c] = acc[b];

    } else if (blk < 144) {
        // ---- unary slots: one (i, slot, batch-half); 16 batches x 128 features; 2 accs ----
        const int  r     = blk - 112;
        const bool slot1 = (r >= 16);
        const int  rr    = r & 15;
        const int  i     = rr >> 1;
        const int  b0    = (rr & 1) * 16;
        const int  tbase = slot1 ? 192 : 64;
        const int  bg    = g * 2;

        #pragma unroll
        for (int it = 0; it < (16 * P1) / NT; it++) {
            const int idx = it * NT + tid;
            const int b = idx >> 7, f = idx & 127;
            xs[idx] = unary[((b0 + b) * NN + i) * P1 + f];
        }
        #pragma unroll
        for (int it = 0; it < (P1 * CC) / NT; it++) {
            const int idx = it * NT + tid;
            const float t = fast_tanh(kern[(tbase + (idx >> 7)) * CC + (idx & 127)]);
            tq[idx] = make_float2(t, fmaf(-t, t, 1.0f));
        }
        __syncthreads();

        float acc[2];
        #pragma unroll
        for (int b = 0; b < 2; b++) acc[b] = 1e30f;

        #pragma unroll
        for (int f2 = 0; f2 < P1 / 2; f2++) {
            const float2 ta = tq[(2 * f2) * CC + c];
            const float2 tb = tq[(2 * f2 + 1) * CC + c];
            #pragma unroll
            for (int b = 0; b < 2; b++) {
                const float2 x2 = xs2[(bg + b) * 64 + f2];
                acc[b] = fminf(acc[b], fmaf(x2.x, ta.x, ta.y));
                acc[b] = fminf(acc[b], fmaf(x2.y, tb.x, tb.y));
            }
        }

        float* dst = slot1 ? g_U1 : g_U0;
        #pragma unroll
        for (int b = 0; b < 2; b++)
            dst[((b0 + bg + b) * NN + i) * CC + c] = acc[b];

    } else {
        // ---- nullary slot: 32 batches x 64 features; 4 accs/thread ----
        const int bg = g * 4;

        #pragma unroll
        for (int it = 0; it < (PB * P0) / NT; it++) {
            const int idx = it * NT + tid;
            const int b = idx >> 6, f = idx & 63;
            xs[idx] = nullary[b * P0 + f];
        }
        #pragma unroll
        for (int it = 0; it < (P0 * CC) / NT; it++) {
            const int idx = it * NT + tid;
            const float t = fast_tanh(kern[(idx >> 7) * CC + (idx & 127)]);
            tq[idx] = make_float2(t, fmaf(-t, t, 1.0f));
        }
        __syncthreads();

        float acc[4];
        #pragma unroll
        for (int b = 0; b < 4; b++) acc[b] = 1e30f;

        #pragma unroll
        for (int f2 = 0; f2 < P0 / 2; f2++) {
            const float2 ta = tq[(2 * f2) * CC + c];
            const float2 tb = tq[(2 * f2 + 1) * CC + c];
            #pragma unroll
            for (int b = 0; b < 4; b++) {
                const float2 x2 = xs2[(bg + b) * 32 + f2];
                acc[b] = fminf(acc[b], fmaf(x2.x, ta.x, ta.y));
                acc[b] = fminf(acc[b], fmaf(x2.y, tb.x, tb.y));
            }
        }

        #pragma unroll
        for (int b = 0; b < 4; b++)
            g_N0[(bg + b) * CC + c] = acc[b];
    }

    // ================= Grid soft-barrier (145 blocks, single wave) =================
    __threadfence();
    __syncthreads();
    if (tid == 0) atomicAdd(&g_arrive, 1);

    if (blk >= PB) return;   // only blocks 0..31 combine

    if (tid == 0) {
        while (*((volatile int*)&g_arrive) != GRID) { }
    }
    __syncthreads();
    __threadfence();

    // ================= Phase 2: combine for batch b = blk =================
    {
        const int b = blk;
        float u0[NN], u1[NN];
        #pragma unroll
        for (int ii = 0; ii < NN; ii++) {
            u0[ii] = g_U0[(b * NN + ii) * CC + c];
            u1[ii] = g_U1[(b * NN + ii) * CC + c];
        }
        const float n0 = g_N0[b * CC + c];

        // group g handles k in [g*7, g*7+7)
        float mx = -1e30f;
        const int k0 = g * 7;
        #pragma unroll
        for (int kk = 0; kk < 7; kk++) {
            const int k  = k0 + kk;
            const int i  = k / 7;
            const int r  = k % 7;
            const int j  = r + (r >= i);
            const int rv = j * 7 + (i - (i > j));  // reversed-pair index
            const float b0v = g_B0[(b * KK + k)  * CC + c];
            const float b1v = g_B1[(b * KK + rv) * CC + c];
            float v = fminf(fminf(b0v, b1v), fminf(u0[i], u1[j]));
            v = fminf(v, n0);
            mx = fmaxf(mx, v);
        }
        xs[g * CC + c] = mx;
        __syncthreads();
        if (tid < CC) {
            float m = xs[c];
            #pragma unroll
            for (int gg = 1; gg < 8; gg++)
                m = fmaxf(m, xs[gg * CC + c]);
            out[b * CC + c] = m;
        }
    }

    // ================= Counter reset for graph replay =================
    __syncthreads();
    if (tid == 0) {
        const int old = atomicAdd(&g_done, 1);
        if (old == PB - 1) {
            atomicExch(&g_arrive, 0);
            atomicExch(&g_done, 0);
        }
    }
}

extern "C" void kernel_launch(void* const* d_in, const int* in_sizes, int n_in,
                              void* d_out, int out_size) {
    const float* nullary = (const float*)d_in[0];  // (32, 64)
    const float* unary   = (const float*)d_in[1];  // (32, 8, 128)
    const float* binary  = (const float*)d_in[2];  // (32, 8, 7, 64)
    const float* kern    = (const float*)d_in[3];  // (448, 128)
    float* out = (float*)d_out;                    // (32, 128)

    cudaFuncSetAttribute(fused_k, cudaFuncAttributeMaxDynamicSharedMemorySize, SMEM_BYTES);
    fused_k<<<GRID, NT, SMEM_BYTES>>>(nullary, unary, binary, kern, out);
}

// round 8
// speedup vs baseline: 2.0284x; 2.0284x over previous
#include <cuda_runtime.h>
#include <cuda_bf16.h>

// Problem constants
#define PB    32    // batch
#define NN    8     // objects
#define P0    64
#define P1    128
#define P2    64
#define CC    128   // channels
#define KK    56    // permutations of (8,2)
#define NT    512   // threads: 4 f-chunks x 128 channels
#define GRID  145   // 112 binary + 32 unary + 1 nullary (single wave on 148 SMs)

// Scratch (allocation-free: __device__ globals)
__device__ float g_N0[PB * CC];
__device__ float g_U0[PB * NN * CC];
__device__ float g_U1[PB * NN * CC];
__device__ float g_B0[PB * KK * CC];
__device__ float g_B1[PB * KK * CC];
__device__ int   g_arrive;   // zero-init; self-reset each launch
__device__ int   g_done;

// tanh(x) = 1 - 2/(exp(2x)+1). Safe at large |x|.
__device__ __forceinline__ float fast_tanh(float x) {
    const float e = __expf(2.0f * x);
    return 1.0f - __fdividef(2.0f, e + 1.0f);
}

__global__ __launch_bounds__(NT) void fused_k(const float* __restrict__ nullary,
                                              const float* __restrict__ unary,
                                              const float* __restrict__ binary,
                                              const float* __restrict__ kern,
                                              float* __restrict__ out) {
    __shared__ __align__(16) float xs[2048];          // 8 KB  x staging (b-major)
    __shared__ __align__(16) float buf[2 * 32 * 128]; // 32 KB fc-reduction buffer

    const int blk = blockIdx.x;
    const int tid = threadIdx.x;
    const int fc  = tid >> 7;     // feature chunk 0..3
    const int c   = tid & 127;    // channel
    const float4* xs4 = reinterpret_cast<const float4*>(xs);

    // ================= Phase 1: slot-partial mins =================
    if (blk < 112) {
        // ---- binary slots: one pair m; 32 b x 64 f; thread owns 16 f, loops 32 b ----
        const bool slot1 = (blk >= 56);
        const int  m     = slot1 ? blk - 56 : blk;
        const int  i     = m / 7;
        const int  jp    = m % 7;
        const int  tbase = (slot1 ? 384 : 320) + fc * 16;

        #pragma unroll
        for (int it = 0; it < 4; it++) {
            const int idx = it * NT + tid;
            const int b = idx >> 6, f = idx & 63;
            xs[idx] = binary[((b * NN + i) * (NN - 1) + jp) * P2 + f];
        }

        float t[16], q[16];
        #pragma unroll
        for (int ff = 0; ff < 16; ff++) {
            const float tt = fast_tanh(kern[(tbase + ff) * CC + c]);
            t[ff] = tt;
            q[ff] = fmaf(-tt, tt, 1.0f);
        }
        __syncthreads();

        float a[PB];
        #pragma unroll
        for (int b = 0; b < PB; b++) a[b] = 1e30f;

        #pragma unroll
        for (int b = 0; b < PB; b++) {
            #pragma unroll
            for (int v = 0; v < 4; v++) {
                const float4 xv = xs4[b * 16 + fc * 4 + v];  // warp-broadcast
                a[b] = fminf(a[b], fmaf(xv.x, t[4 * v + 0], q[4 * v + 0]));
                a[b] = fminf(a[b], fmaf(xv.y, t[4 * v + 1], q[4 * v + 1]));
                a[b] = fminf(a[b], fmaf(xv.z, t[4 * v + 2], q[4 * v + 2]));
                a[b] = fminf(a[b], fmaf(xv.w, t[4 * v + 3], q[4 * v + 3]));
            }
        }

        // fc-reduction: 4 chunks -> 2 -> 1
        if (fc < 2) {
            #pragma unroll
            for (int b = 0; b < PB; b++) buf[fc * 4096 + b * 128 + c] = a[b];
        }
        __syncthreads();
        if (fc >= 2) {
            #pragma unroll
            for (int b = 0; b < PB; b++) {
                const int o = (fc - 2) * 4096 + b * 128 + c;
                buf[o] = fminf(buf[o], a[b]);
            }
        }
        __syncthreads();
        if (fc < 2) {
            float* dst = slot1 ? g_B1 : g_B0;
            #pragma unroll
            for (int bb = 0; bb < 16; bb++) {
                const int b = fc * 16 + bb;
                dst[(b * KK + m) * CC + c] =
                    fminf(buf[b * 128 + c], buf[4096 + b * 128 + c]);
            }
        }

    } else if (blk < 144) {
        // ---- unary slots: one (i, slot, b-half); 16 b x 128 f; thread owns 32 f ----
        const int  r     = blk - 112;
        const bool slot1 = (r >= 16);
        const int  rr    = r & 15;
        const int  i     = rr >> 1;
        const int  b0    = (rr & 1) * 16;
        const int  tbase = (slot1 ? 192 : 64) + fc * 32;

        #pragma unroll
        for (int it = 0; it < 4; it++) {
            const int idx = it * NT + tid;
            const int b = idx >> 7, f = idx & 127;
            xs[idx] = unary[((b0 + b) * NN + i) * P1 + f];
        }

        float t[32], q[32];
        #pragma unroll
        for (int ff = 0; ff < 32; ff++) {
            const float tt = fast_tanh(kern[(tbase + ff) * CC + c]);
            t[ff] = tt;
            q[ff] = fmaf(-tt, tt, 1.0f);
        }
        __syncthreads();

        float a[16];
        #pragma unroll
        for (int b = 0; b < 16; b++) a[b] = 1e30f;

        #pragma unroll
        for (int b = 0; b < 16; b++) {
            #pragma unroll
            for (int v = 0; v < 8; v++) {
                const float4 xv = xs4[b * 32 + fc * 8 + v];  // warp-broadcast
                a[b] = fminf(a[b], fmaf(xv.x, t[4 * v + 0], q[4 * v + 0]));
                a[b] = fminf(a[b], fmaf(xv.y, t[4 * v + 1], q[4 * v + 1]));
                a[b] = fminf(a[b], fmaf(xv.z, t[4 * v + 2], q[4 * v + 2]));
                a[b] = fminf(a[b], fmaf(xv.w, t[4 * v + 3], q[4 * v + 3]));
            }
        }

        if (fc < 2) {
            #pragma unroll
            for (int b = 0; b < 16; b++) buf[fc * 2048 + b * 128 + c] = a[b];
        }
        __syncthreads();
        if (fc >= 2) {
            #pragma unroll
            for (int b = 0; b < 16; b++) {
                const int o = (fc - 2) * 2048 + b * 128 + c;
                buf[o] = fminf(buf[o], a[b]);
            }
        }
        __syncthreads();
        if (fc < 2) {
            float* dst = slot1 ? g_U1 : g_U0;
            #pragma unroll
            for (int bb = 0; bb < 8; bb++) {
                const int b = fc * 8 + bb;
                dst[((b0 + b) * NN + i) * CC + c] =
                    fminf(buf[b * 128 + c], buf[2048 + b * 128 + c]);
            }
        }

    } else {
        // ---- nullary slot: 32 b x 64 f; thread owns 16 f ----
        const int tbase = fc * 16;

        #pragma unroll
        for (int it = 0; it < 4; it++) {
            const int idx = it * NT + tid;
            const int b = idx >> 6, f = idx & 63;
            xs[idx] = nullary[b * P0 + f];
        }

        float t[16], q[16];
        #pragma unroll
        for (int ff = 0; ff < 16; ff++) {
            const float tt = fast_tanh(kern[(tbase + ff) * CC + c]);
            t[ff] = tt;
            q[ff] = fmaf(-tt, tt, 1.0f);
        }
        __syncthreads();

        float a[PB];
        #pragma unroll
        for (int b = 0; b < PB; b++) a[b] = 1e30f;

        #pragma unroll
        for (int b = 0; b < PB; b++) {
            #pragma unroll
            for (int v = 0; v < 4; v++) {
                const float4 xv = xs4[b * 16 + fc * 4 + v];
                a[b] = fminf(a[b], fmaf(xv.x, t[4 * v + 0], q[4 * v + 0]));
                a[b] = fminf(a[b], fmaf(xv.y, t[4 * v + 1], q[4 * v + 1]));
                a[b] = fminf(a[b], fmaf(xv.z, t[4 * v + 2], q[4 * v + 2]));
                a[b] = fminf(a[b], fmaf(xv.w, t[4 * v + 3], q[4 * v + 3]));
            }
        }

        if (fc < 2) {
            #pragma unroll
            for (int b = 0; b < PB; b++) buf[fc * 4096 + b * 128 + c] = a[b];
        }
        __syncthreads();
        if (fc >= 2) {
            #pragma unroll
            for (int b = 0; b < PB; b++) {
                const int o = (fc - 2) * 4096 + b * 128 + c;
                buf[o] = fminf(buf[o], a[b]);
            }
        }
        __syncthreads();
        if (fc < 2) {
            #pragma unroll
            for (int bb = 0; bb < 16; bb++) {
                const int b = fc * 16 + bb;
                g_N0[b * CC + c] =
                    fminf(buf[b * 128 + c], buf[4096 + b * 128 + c]);
            }
        }
    }

    // ================= Grid soft-barrier (145 blocks, single wave) =================
    __threadfence();
    __syncthreads();
    if (tid == 0) atomicAdd(&g_arrive, 1);

    if (blk >= PB) return;   // only blocks 0..31 combine

    if (tid == 0) {
        while (*((volatile int*)&g_arrive) != GRID) { }
    }
    __syncthreads();
    __threadfence();

    // ================= Phase 2: combine for batch b = blk =================
    {
        const int b = blk;
        float u0[NN], u1[NN];
        #pragma unroll
        for (int ii = 0; ii < NN; ii++) {
            u0[ii] = g_U0[(b * NN + ii) * CC + c];
            u1[ii] = g_U1[(b * NN + ii) * CC + c];
        }
        const float n0 = g_N0[b * CC + c];

        // f-chunk group fc handles k in [fc*14, fc*14+14)
        float mx = -1e30f;
        const int k0 = fc * 14;
        #pragma unroll
        for (int kk = 0; kk < 14; kk++) {
            const int k  = k0 + kk;
            const int i  = k / 7;
            const int r  = k % 7;
            const int j  = r + (r >= i);
            const int rv = j * 7 + (i - (i > j));  // reversed-pair index
            const float b0v = g_B0[(b * KK + k)  * CC + c];
            const float b1v = g_B1[(b * KK + rv) * CC + c];
            float v = fminf(fminf(b0v, b1v), fminf(u0[i], u1[j]));
            v = fminf(v, n0);
            mx = fmaxf(mx, v);
        }
        buf[fc * CC + c] = mx;
        __syncthreads();
        if (tid < CC) {
            const float m = fmaxf(fmaxf(buf[c], buf[CC + c]),
                                  fmaxf(buf[2 * CC + c], buf[3 * CC + c]));
            out[b * CC + c] = m;
        }
    }

    // ================= Counter reset for graph replay =================
    __syncthreads();
    if (tid == 0) {
        const int old = atomicAdd(&g_done, 1);
        if (old == PB - 1) {
            atomicExch(&g_arrive, 0);
            atomicExch(&g_done, 0);
        }
    }
}

extern "C" void kernel_launch(void* const* d_in, const int* in_sizes, int n_in,
                              void* d_out, int out_size) {
    const float* nullary = (const float*)d_in[0];  // (32, 64)
    const float* unary   = (const float*)d_in[1];  // (32, 8, 128)
    const float* binary  = (const float*)d_in[2];  // (32, 8, 7, 64)
    const float* kern    = (const float*)d_in[3];  // (448, 128)
    float* out = (float*)d_out;                    // (32, 128)

    fused_k<<<GRID, NT>>>(nullary, unary, binary, kern, out);
}

// round 9
// speedup vs baseline: 2.1208x; 1.0455x over previous
#include <cuda_runtime.h>
#include <cuda_bf16.h>

// Problem constants
#define PB    32    // batch
#define NN    8     // objects
#define P0    64
#define P1    128
#define P2    64
#define CC    128   // channels
#define KK    56    // permutations of (8,2)
#define NT    1024  // threads: 8 subgroups x 128 channels
#define GRID  145   // 112 binary + 32 unary + 1 nullary (single wave on 148 SMs)

// Scratch (allocation-free: __device__ globals)
__device__ float g_N0[PB * CC];
__device__ float g_U0[PB * NN * CC];
__device__ float g_U1[PB * NN * CC];
__device__ float g_B0[PB * KK * CC];
__device__ float g_B1[PB * KK * CC];
__device__ int   g_arrive;   // zero-init; self-reset each launch
__device__ int   g_done;

// tanh(x) = 1 - 2/(exp(2x)+1). Safe at large |x|.
__device__ __forceinline__ float fast_tanh(float x) {
    const float e = __expf(2.0f * x);
    return 1.0f - __fdividef(2.0f, e + 1.0f);
}

__global__ __launch_bounds__(NT) void fused_k(const float* __restrict__ nullary,
                                              const float* __restrict__ unary,
                                              const float* __restrict__ binary,
                                              const float* __restrict__ kern,
                                              float* __restrict__ out) {
    __shared__ __align__(16) float xs[2048];   // 8 KB  x staging (b-major)
    __shared__ __align__(16) float buf[8192];  // 32 KB reduction buffer

    const int blk = blockIdx.x;
    const int tid = threadIdx.x;
    const int u   = tid >> 7;     // subgroup 0..7
    const int c   = tid & 127;    // channel
    const float4* xs4 = reinterpret_cast<const float4*>(xs);

    // ================= Phase 1: slot-partial mins =================
    if (blk < 112) {
        // ---- binary slots: one pair m; subgroup = (f-chunk 16, b-half 16) ----
        const bool slot1 = (blk >= 56);
        const int  m     = slot1 ? blk - 56 : blk;
        const int  i     = m / 7;
        const int  jp    = m % 7;
        const int  fh    = u & 3;           // f-chunk 0..3 (16 f each)
        const int  bh    = u >> 2;          // b-half 0..1 (16 b each)
        const int  bbase = bh * 16;
        const int  tbase = (slot1 ? 384 : 320) + fh * 16;

        #pragma unroll
        for (int it = 0; it < 2; it++) {
            const int idx = it * NT + tid;
            const int b = idx >> 6, f = idx & 63;
            xs[idx] = binary[((b * NN + i) * (NN - 1) + jp) * P2 + f];
        }

        float t[16], q[16];
        #pragma unroll
        for (int ff = 0; ff < 16; ff++) {
            const float tt = fast_tanh(kern[(tbase + ff) * CC + c]);
            t[ff] = tt;
            q[ff] = fmaf(-tt, tt, 1.0f);
        }
        __syncthreads();

        float a[16];
        #pragma unroll
        for (int b = 0; b < 16; b++) a[b] = 1e30f;

        #pragma unroll
        for (int b = 0; b < 16; b++) {
            #pragma unroll
            for (int v = 0; v < 4; v++) {
                const float4 xv = xs4[(bbase + b) * 16 + fh * 4 + v];  // warp-broadcast
                a[b] = fminf(a[b], fmaf(xv.x, t[4 * v + 0], q[4 * v + 0]));
                a[b] = fminf(a[b], fmaf(xv.y, t[4 * v + 1], q[4 * v + 1]));
                a[b] = fminf(a[b], fmaf(xv.z, t[4 * v + 2], q[4 * v + 2]));
                a[b] = fminf(a[b], fmaf(xv.w, t[4 * v + 3], q[4 * v + 3]));
            }
        }

        // reduce 4 f-chunks -> 1 per b-half: buf[bh][s][b][c], s in {0,1}
        if (fh >= 2) {
            #pragma unroll
            for (int b = 0; b < 16; b++)
                buf[((bh * 2 + (fh - 2)) * 16 + b) * 128 + c] = a[b];
        }
        __syncthreads();
        if (fh < 2) {
            #pragma unroll
            for (int b = 0; b < 16; b++)
                a[b] = fminf(a[b], buf[((bh * 2 + fh) * 16 + b) * 128 + c]);
        }
        __syncthreads();
        if (fh == 1) {
            #pragma unroll
            for (int b = 0; b < 16; b++)
                buf[((bh * 2) * 16 + b) * 128 + c] = a[b];
        }
        __syncthreads();
        if (fh == 0) {
            float* dst = slot1 ? g_B1 : g_B0;
            #pragma unroll
            for (int b = 0; b < 16; b++) {
                const float r = fminf(a[b], buf[((bh * 2) * 16 + b) * 128 + c]);
                dst[((bbase + b) * KK + m) * CC + c] = r;
            }
        }

    } else if (blk < 144) {
        // ---- unary slots: one (i, slot, b-half16); 8 f-chunks of 16 f ----
        const int  r     = blk - 112;
        const bool slot1 = (r >= 16);
        const int  rr    = r & 15;
        const int  i     = rr >> 1;
        const int  b0    = (rr & 1) * 16;
        const int  tbase = (slot1 ? 192 : 64) + u * 16;

        #pragma unroll
        for (int it = 0; it < 2; it++) {
            const int idx = it * NT + tid;
            const int b = idx >> 7, f = idx & 127;
            xs[idx] = unary[((b0 + b) * NN + i) * P1 + f];
        }

        float t[16], q[16];
        #pragma unroll
        for (int ff = 0; ff < 16; ff++) {
            const float tt = fast_tanh(kern[(tbase + ff) * CC + c]);
            t[ff] = tt;
            q[ff] = fmaf(-tt, tt, 1.0f);
        }
        __syncthreads();

        float a[16];
        #pragma unroll
        for (int b = 0; b < 16; b++) a[b] = 1e30f;

        #pragma unroll
        for (int b = 0; b < 16; b++) {
            #pragma unroll
            for (int v = 0; v < 4; v++) {
                const float4 xv = xs4[b * 32 + u * 4 + v];  // warp-broadcast
                a[b] = fminf(a[b], fmaf(xv.x, t[4 * v + 0], q[4 * v + 0]));
                a[b] = fminf(a[b], fmaf(xv.y, t[4 * v + 1], q[4 * v + 1]));
                a[b] = fminf(a[b], fmaf(xv.z, t[4 * v + 2], q[4 * v + 2]));
                a[b] = fminf(a[b], fmaf(xv.w, t[4 * v + 3], q[4 * v + 3]));
            }
        }

        // reduce 8 f-chunks -> 1: buf[s][b][c], s in 0..3
        if (u >= 4) {
            #pragma unroll
            for (int b = 0; b < 16; b++)
                buf[((u - 4) * 16 + b) * 128 + c] = a[b];
        }
        __syncthreads();
        if (u < 4) {
            #pragma unroll
            for (int b = 0; b < 16; b++)
                a[b] = fminf(a[b], buf[(u * 16 + b) * 128 + c]);
        }
        __syncthreads();
        if (u == 2 || u == 3) {
            #pragma unroll
            for (int b = 0; b < 16; b++)
                buf[((u - 2) * 16 + b) * 128 + c] = a[b];
        }
        __syncthreads();
        if (u < 2) {
            #pragma unroll
            for (int b = 0; b < 16; b++)
                a[b] = fminf(a[b], buf[(u * 16 + b) * 128 + c]);
        }
        __syncthreads();
        if (u == 1) {
            #pragma unroll
            for (int b = 0; b < 16; b++)
                buf[b * 128 + c] = a[b];
        }
        __syncthreads();
        if (u == 0) {
            float* dst = slot1 ? g_U1 : g_U0;
            #pragma unroll
            for (int b = 0; b < 16; b++) {
                const float rr2 = fminf(a[b], buf[b * 128 + c]);
                dst[((b0 + b) * NN + i) * CC + c] = rr2;
            }
        }

    } else {
        // ---- nullary slot: 32 b x 64 f; subgroup = (f-chunk 16, b-half 16) ----
        const int fh    = u & 3;
        const int bh    = u >> 2;
        const int bbase = bh * 16;
        const int tbase = fh * 16;

        #pragma unroll
        for (int it = 0; it < 2; it++) {
            const int idx = it * NT + tid;
            const int b = idx >> 6, f = idx & 63;
            xs[idx] = nullary[b * P0 + f];
        }

        float t[16], q[16];
        #pragma unroll
        for (int ff = 0; ff < 16; ff++) {
            const float tt = fast_tanh(kern[(tbase + ff) * CC + c]);
            t[ff] = tt;
            q[ff] = fmaf(-tt, tt, 1.0f);
        }
        __syncthreads();

        float a[16];
        #pragma unroll
        for (int b = 0; b < 16; b++) a[b] = 1e30f;

        #pragma unroll
        for (int b = 0; b < 16; b++) {
            #pragma unroll
            for (int v = 0; v < 4; v++) {
                const float4 xv = xs4[(bbase + b) * 16 + fh * 4 + v];
                a[b] = fminf(a[b], fmaf(xv.x, t[4 * v + 0], q[4 * v + 0]));
                a[b] = fminf(a[b], fmaf(xv.y, t[4 * v + 1], q[4 * v + 1]));
                a[b] = fminf(a[b], fmaf(xv.z, t[4 * v + 2], q[4 * v + 2]));
                a[b] = fminf(a[b], fmaf(xv.w, t[4 * v + 3], q[4 * v + 3]));
            }
        }

        if (fh >= 2) {
            #pragma unroll
            for (int b = 0; b < 16; b++)
                buf[((bh * 2 + (fh - 2)) * 16 + b) * 128 + c] = a[b];
        }
        __syncthreads();
        if (fh < 2) {
            #pragma unroll
            for (int b = 0; b < 16; b++)
                a[b] = fminf(a[b], buf[((bh * 2 + fh) * 16 + b) * 128 + c]);
        }
        __syncthreads();
        if (fh == 1) {
            #pragma unroll
            for (int b = 0; b < 16; b++)
                buf[((bh * 2) * 16 + b) * 128 + c] = a[b];
        }
        __syncthreads();
        if (fh == 0) {
            #pragma unroll
            for (int b = 0; b < 16; b++) {
                const float r = fminf(a[b], buf[((bh * 2) * 16 + b) * 128 + c]);
                g_N0[(bbase + b) * CC + c] = r;
            }
        }
    }

    // ================= Grid soft-barrier (145 blocks, single wave) =================
    __threadfence();
    __syncthreads();
    if (tid == 0) atomicAdd(&g_arrive, 1);

    if (blk >= PB) return;   // only blocks 0..31 combine

    if (tid == 0) {
        while (*((volatile int*)&g_arrive) != GRID) { }
    }
    __syncthreads();
    __threadfence();

    // ================= Phase 2: combine for batch b = blk =================
    {
        const int b = blk;
        float u0[NN], u1[NN];
        #pragma unroll
        for (int ii = 0; ii < NN; ii++) {
            u0[ii] = g_U0[(b * NN + ii) * CC + c];
            u1[ii] = g_U1[(b * NN + ii) * CC + c];
        }
        const float n0 = g_N0[b * CC + c];

        // subgroup u handles k in [u*7, u*7+7)
        float mx = -1e30f;
        const int k0 = u * 7;
        #pragma unroll
        for (int kk = 0; kk < 7; kk++) {
            const int k  = k0 + kk;
            const int i  = k / 7;
            const int r  = k % 7;
            const int j  = r + (r >= i);
            const int rv = j * 7 + (i - (i > j));  // reversed-pair index
            const float b0v = g_B0[(b * KK + k)  * CC + c];
            const float b1v = g_B1[(b * KK + rv) * CC + c];
            float v = fminf(fminf(b0v, b1v), fminf(u0[i], u1[j]));
            v = fminf(v, n0);
            mx = fmaxf(mx, v);
        }
        buf[u * CC + c] = mx;
        __syncthreads();
        if (tid < CC) {
            float m = buf[c];
            #pragma unroll
            for (int gg = 1; gg < 8; gg++)
                m = fmaxf(m, buf[gg * CC + c]);
            out[b * CC + c] = m;
        }
    }

    // ================= Counter reset for graph replay =================
    __syncthreads();
    if (tid == 0) {
        const int old = atomicAdd(&g_done, 1);
        if (old == PB - 1) {
            atomicExch(&g_arrive, 0);
            atomicExch(&g_done, 0);
        }
    }
}

extern "C" void kernel_launch(void* const* d_in, const int* in_sizes, int n_in,
                              void* d_out, int out_size) {
    const float* nullary = (const float*)d_in[0];  // (32, 64)
    const float* unary   = (const float*)d_in[1];  // (32, 8, 128)
    const float* binary  = (const float*)d_in[2];  // (32, 8, 7, 64)
    const float* kern    = (const float*)d_in[3];  // (448, 128)
    float* out = (float*)d_out;                    // (32, 128)

    fused_k<<<GRID, NT>>>(nullary, unary, binary, kern, out);
}

// round 13
// speedup vs baseline: 2.3642x; 1.1148x over previous
#include <cuda_runtime.h>
#include <cuda_bf16.h>

// Problem constants
#define PB    32    // batch
#define NN    8     // objects
#define P0    64
#define P1    128
#define P2    64
#define CC    128   // channels
#define KK    56    // permutations of (8,2)
#define NT    1024  // threads: 8 subgroups x 128 channels
#define GRID  145   // 112 binary + 32 unary + 1 nullary (single wave on 148 SMs)

// Scratch (allocation-free: __device__ globals)
__device__ float g_N0[PB * CC];
__device__ float g_U0[PB * NN * CC];
__device__ float g_U1[PB * NN * CC];
__device__ float g_B0[PB * KK * CC];
__device__ float g_B1[PB * KK * CC];
__device__ int   g_arrive;   // zero-init; self-reset each launch
__device__ int   g_done;

// tanh(x) = 1 - 2/(exp(2x)+1). Safe at large |x|.
__device__ __forceinline__ float fast_tanh(float x) {
    const float e = __expf(2.0f * x);
    return 1.0f - __fdividef(2.0f, e + 1.0f);
}

// 4 weighted-truth FMAs + tree min, folded into acc.
__device__ __forceinline__ float wt_min4(float acc, float4 xv,
                                         const float* t, const float* q, int o) {
    const float w0 = fmaf(xv.x, t[o + 0], q[o + 0]);
    const float w1 = fmaf(xv.y, t[o + 1], q[o + 1]);
    const float w2 = fmaf(xv.z, t[o + 2], q[o + 2]);
    const float w3 = fmaf(xv.w, t[o + 3], q[o + 3]);
    return fminf(acc, fminf(fminf(w0, w1), fminf(w2, w3)));
}

__global__ __launch_bounds__(NT) void fused_k(const float* __restrict__ nullary,
                                              const float* __restrict__ unary,
                                              const float* __restrict__ binary,
                                              const float* __restrict__ kern,
                                              float* __restrict__ out) {
    __shared__ __align__(16) float xs[2048];   // 8 KB  x staging (b-major)
    __shared__ __align__(16) float buf[8192];  // 32 KB reduction buffer

    const int blk = blockIdx.x;
    const int tid = threadIdx.x;
    const int u   = tid >> 7;     // subgroup 0..7
    const int c   = tid & 127;    // channel
    const float4* xs4 = reinterpret_cast<const float4*>(xs);
    float4* xs4w = reinterpret_cast<float4*>(xs);

    // ================= Phase 1: slot-partial mins =================
    if (blk < 112) {
        // ---- binary slots: one pair m; subgroup = (f-chunk 16, b-half 16) ----
        const bool slot1 = (blk >= 56);
        const int  m     = slot1 ? blk - 56 : blk;
        const int  i     = m / 7;
        const int  jp    = m % 7;
        const int  fh    = u & 3;           // f-chunk 0..3 (16 f each)
        const int  bh    = u >> 2;          // b-half 0..1 (16 b each)
        const int  bbase = bh * 16;
        const int  tbase = (slot1 ? 384 : 320) + fh * 16;

        // 1) kern loads issued first (latency covered by staging below)
        float kr[16];
        #pragma unroll
        for (int ff = 0; ff < 16; ff++) kr[ff] = kern[(tbase + ff) * CC + c];

        // 2) x staging: 512 float4
        if (tid < 512) {
            const int b = tid >> 4, f4 = tid & 15;
            xs4w[tid] = *reinterpret_cast<const float4*>(
                binary + ((b * NN + i) * (NN - 1) + jp) * P2 + f4 * 4);
        }

        // 3) tanh on registers
        float t[16], q[16];
        #pragma unroll
        for (int ff = 0; ff < 16; ff++) {
            const float tt = fast_tanh(kr[ff]);
            t[ff] = tt;
            q[ff] = fmaf(-tt, tt, 1.0f);
        }
        __syncthreads();

        float a[16];
        #pragma unroll
        for (int b = 0; b < 16; b++) a[b] = 1e30f;

        #pragma unroll
        for (int b = 0; b < 16; b++) {
            #pragma unroll
            for (int v = 0; v < 4; v++)
                a[b] = wt_min4(a[b], xs4[(bbase + b) * 16 + fh * 4 + v], t, q, 4 * v);
        }

        // reduce 4 f-chunks -> 1 per b-half
        if (fh >= 2) {
            #pragma unroll
            for (int b = 0; b < 16; b++)
                buf[((bh * 2 + (fh - 2)) * 16 + b) * 128 + c] = a[b];
        }
        __syncthreads();
        if (fh < 2) {
            #pragma unroll
            for (int b = 0; b < 16; b++)
                a[b] = fminf(a[b], buf[((bh * 2 + fh) * 16 + b) * 128 + c]);
        }
        __syncthreads();
        if (fh == 1) {
            #pragma unroll
            for (int b = 0; b < 16; b++)
                buf[((bh * 2) * 16 + b) * 128 + c] = a[b];
        }
        __syncthreads();
        if (fh == 0) {
            float* dst = slot1 ? g_B1 : g_B0;
            #pragma unroll
            for (int b = 0; b < 16; b++) {
                const float r = fminf(a[b], buf[((bh * 2) * 16 + b) * 128 + c]);
                dst[((bbase + b) * KK + m) * CC + c] = r;
            }
        }

    } else if (blk < 144) {
        // ---- unary slots: one (i, slot, b-half16); 8 f-chunks of 16 f ----
        const int  r     = blk - 112;
        const bool slot1 = (r >= 16);
        const int  rr    = r & 15;
        const int  i     = rr >> 1;
        const int  b0    = (rr & 1) * 16;
        const int  tbase = (slot1 ? 192 : 64) + u * 16;

        float kr[16];
        #pragma unroll
        for (int ff = 0; ff < 16; ff++) kr[ff] = kern[(tbase + ff) * CC + c];

        if (tid < 512) {
            const int b = tid >> 5, f4 = tid & 31;
            xs4w[tid] = *reinterpret_cast<const float4*>(
                unary + ((b0 + b) * NN + i) * P1 + f4 * 4);
        }

        float t[16], q[16];
        #pragma unroll
        for (int ff = 0; ff < 16; ff++) {
            const float tt = fast_tanh(kr[ff]);
            t[ff] = tt;
            q[ff] = fmaf(-tt, tt, 1.0f);
        }
        __syncthreads();

        float a[16];
        #pragma unroll
        for (int b = 0; b < 16; b++) a[b] = 1e30f;

        #pragma unroll
        for (int b = 0; b < 16; b++) {
            #pragma unroll
            for (int v = 0; v < 4; v++)
                a[b] = wt_min4(a[b], xs4[b * 32 + u * 4 + v], t, q, 4 * v);
        }

        // reduce 8 f-chunks -> 1
        if (u >= 4) {
            #pragma unroll
            for (int b = 0; b < 16; b++)
                buf[((u - 4) * 16 + b) * 128 + c] = a[b];
        }
        __syncthreads();
        if (u < 4) {
            #pragma unroll
            for (int b = 0; b < 16; b++)
                a[b] = fminf(a[b], buf[(u * 16 + b) * 128 + c]);
        }
        __syncthreads();
        if (u == 2 || u == 3) {
            #pragma unroll
            for (int b = 0; b < 16; b++)
                buf[((u - 2) * 16 + b) * 128 + c] = a[b];
        }
        __syncthreads();
        if (u < 2) {
            #pragma unroll
            for (int b = 0; b < 16; b++)
                a[b] = fminf(a[b], buf[(u * 16 + b) * 128 + c]);
        }
        __syncthreads();
        if (u == 1) {
            #pragma unroll
            for (int b = 0; b < 16; b++)
                buf[b * 128 + c] = a[b];
        }
        __syncthreads();
        if (u == 0) {
            float* dst = slot1 ? g_U1 : g_U0;
            #pragma unroll
            for (int b = 0; b < 16; b++) {
                const float rr2 = fminf(a[b], buf[b * 128 + c]);
                dst[((b0 + b) * NN + i) * CC + c] = rr2;
            }
        }

    } else {
        // ---- nullary slot: 32 b x 64 f; subgroup = (f-chunk 16, b-half 16) ----
        const int fh    = u & 3;
        const int bh    = u >> 2;
        const int bbase = bh * 16;
        const int tbase = fh * 16;

        float kr[16];
        #pragma unroll
        for (int ff = 0; ff < 16; ff++) kr[ff] = kern[(tbase + ff) * CC + c];

        if (tid < 512) {
            const int b = tid >> 4, f4 = tid & 15;
            xs4w[tid] = *reinterpret_cast<const float4*>(nullary + b * P0 + f4 * 4);
        }

        float t[16], q[16];
        #pragma unroll
        for (int ff = 0; ff < 16; ff++) {
            const float tt = fast_tanh(kr[ff]);
            t[ff] = tt;
            q[ff] = fmaf(-tt, tt, 1.0f);
        }
        __syncthreads();

        float a[16];
        #pragma unroll
        for (int b = 0; b < 16; b++) a[b] = 1e30f;

        #pragma unroll
        for (int b = 0; b < 16; b++) {
            #pragma unroll
            for (int v = 0; v < 4; v++)
                a[b] = wt_min4(a[b], xs4[(bbase + b) * 16 + fh * 4 + v], t, q, 4 * v);
        }

        if (fh >= 2) {
            #pragma unroll
            for (int b = 0; b < 16; b++)
                buf[((bh * 2 + (fh - 2)) * 16 + b) * 128 + c] = a[b];
        }
        __syncthreads();
        if (fh < 2) {
            #pragma unroll
            for (int b = 0; b < 16; b++)
                a[b] = fminf(a[b], buf[((bh * 2 + fh) * 16 + b) * 128 + c]);
        }
        __syncthreads();
        if (fh == 1) {
            #pragma unroll
            for (int b = 0; b < 16; b++)
                buf[((bh * 2) * 16 + b) * 128 + c] = a[b];
        }
        __syncthreads();
        if (fh == 0) {
            #pragma unroll
            for (int b = 0; b < 16; b++) {
                const float r = fminf(a[b], buf[((bh * 2) * 16 + b) * 128 + c]);
                g_N0[(bbase + b) * CC + c] = r;
            }
        }
    }

    // ================= Grid soft-barrier (145 blocks, single wave) =================
    __threadfence();
    __syncthreads();
    if (tid == 0) atomicAdd(&g_arrive, 1);

    if (blk >= PB) return;   // only blocks 0..31 combine

    if (tid == 0) {
        while (*((volatile int*)&g_arrive) != GRID) { }
    }
    __syncthreads();
    __threadfence();

    // ================= Phase 2: combine for batch b = blk =================
    {
        const int b = blk;
        const int k0 = u * 7;   // subgroup handles k in [u*7, u*7+7)

        // Batch all loads first (31 LDGs, high MLP)
        float bv0[7], bv1[7], uu[7];
        #pragma unroll
        for (int kk = 0; kk < 7; kk++) {
            const int k  = k0 + kk;
            const int i  = k / 7;
            const int r  = k % 7;
            const int j  = r + (r >= i);
            const int rv = j * 7 + (i - (i > j));  // reversed-pair index
            bv0[kk] = g_B0[(b * KK + k)  * CC + c];
            bv1[kk] = g_B1[(b * KK + rv) * CC + c];
            uu[kk]  = fminf(g_U0[(b * NN + i) * CC + c],
                            g_U1[(b * NN + j) * CC + c]);
        }
        const float n0 = g_N0[b * CC + c];

        float mx = -1e30f;
        #pragma unroll
        for (int kk = 0; kk < 7; kk++) {
            const float v = fminf(fminf(bv0[kk], bv1[kk]), fminf(uu[kk], n0));
            mx = fmaxf(mx, v);
        }
        buf[u * CC + c] = mx;
        __syncthreads();
        if (tid < CC) {
            float m01 = fmaxf(buf[c],            buf[1 * CC + c]);
            float m23 = fmaxf(buf[2 * CC + c],   buf[3 * CC + c]);
            float m45 = fmaxf(buf[4 * CC + c],   buf[5 * CC + c]);
            float m67 = fmaxf(buf[6 * CC + c],   buf[7 * CC + c]);
            out[b * CC + c] = fmaxf(fmaxf(m01, m23), fmaxf(m45, m67));
        }
    }

    // ================= Counter reset for graph replay =================
    __syncthreads();
    if (tid == 0) {
        const int old = atomicAdd(&g_done, 1);
        if (old == PB - 1) {
            atomicExch(&g_arrive, 0);
            atomicExch(&g_done, 0);
        }
    }
}

extern "C" void kernel_launch(void* const* d_in, const int* in_sizes, int n_in,
                              void* d_out, int out_size) {
    const float* nullary = (const float*)d_in[0];  // (32, 64)
    const float* unary   = (const float*)d_in[1];  // (32, 8, 128)
    const float* binary  = (const float*)d_in[2];  // (32, 8, 7, 64)
    const float* kern    = (const float*)d_in[3];  // (448, 128)
    float* out = (float*)d_out;                    // (32, 128)

    fused_k<<<GRID, NT>>>(nullary, unary, binary, kern, out);
}

// round 14
// speedup vs baseline: 2.5082x; 1.0609x over previous
#include <cuda_runtime.h>
#include <cuda_bf16.h>

// Problem constants
#define PB    32    // batch
#define NN    8     // objects
#define P0    64
#define P1    128
#define P2    64
#define CC    128   // channels
#define KK    56    // permutations of (8,2)
#define NT    1024  // threads: 8 subgroups x 128 channels
#define GRID  145   // 112 binary + 32 unary + 1 nullary (single wave on 148 SMs)

// Scratch (allocation-free: __device__ globals)
__device__ float g_N0[PB * CC];
__device__ float g_U0[PB * NN * CC];
__device__ float g_U1[PB * NN * CC];
__device__ float g_B0[PB * KK * CC];
__device__ float g_B1[PB * KK * CC];
// 8 arrive counters, each on its own 128B line (stride 32 ints) to kill
// L2 atomic serialization + poll contention. Zero-init; self-reset per launch.
__device__ int   g_arr[8 * 32];
__device__ int   g_done;

// tanh(x) = 1 - 2/(exp(2x)+1). Safe at large |x|.
__device__ __forceinline__ float fast_tanh(float x) {
    const float e = __expf(2.0f * x);
    return 1.0f - __fdividef(2.0f, e + 1.0f);
}

// 4 weighted-truth FMAs + tree min, folded into acc.
__device__ __forceinline__ float wt_min4(float acc, float4 xv,
                                         const float* t, const float* q, int o) {
    const float w0 = fmaf(xv.x, t[o + 0], q[o + 0]);
    const float w1 = fmaf(xv.y, t[o + 1], q[o + 1]);
    const float w2 = fmaf(xv.z, t[o + 2], q[o + 2]);
    const float w3 = fmaf(xv.w, t[o + 3], q[o + 3]);
    return fminf(acc, fminf(fminf(w0, w1), fminf(w2, w3)));
}

__global__ __launch_bounds__(NT) void fused_k(const float* __restrict__ nullary,
                                              const float* __restrict__ unary,
                                              const float* __restrict__ binary,
                                              const float* __restrict__ kern,
                                              float* __restrict__ out) {
    __shared__ __align__(16) float xs[2048];   // 8 KB  x staging (b-major)
    __shared__ __align__(16) float buf[8192];  // 32 KB reduction buffer

    const int blk = blockIdx.x;
    const int tid = threadIdx.x;
    const int u   = tid >> 7;     // subgroup 0..7
    const int c   = tid & 127;    // channel
    const float4* xs4 = reinterpret_cast<const float4*>(xs);
    float4* xs4w = reinterpret_cast<float4*>(xs);

    // ================= Phase 1: slot-partial mins =================
    if (blk < 112) {
        // ---- binary slots: one pair m; subgroup = (f-chunk 16, b-half 16) ----
        const bool slot1 = (blk >= 56);
        const int  m     = slot1 ? blk - 56 : blk;
        const int  i     = m / 7;
        const int  jp    = m % 7;
        const int  fh    = u & 3;           // f-chunk 0..3 (16 f each)
        const int  bh    = u >> 2;          // b-half 0..1 (16 b each)
        const int  bbase = bh * 16;
        const int  tbase = (slot1 ? 384 : 320) + fh * 16;

        // 1) kern loads issued first (latency covered by staging below)
        float kr[16];
        #pragma unroll
        for (int ff = 0; ff < 16; ff++) kr[ff] = kern[(tbase + ff) * CC + c];

        // 2) x staging: 512 float4
        if (tid < 512) {
            const int b = tid >> 4, f4 = tid & 15;
            xs4w[tid] = *reinterpret_cast<const float4*>(
                binary + ((b * NN + i) * (NN - 1) + jp) * P2 + f4 * 4);
        }

        // 3) tanh on registers
        float t[16], q[16];
        #pragma unroll
        for (int ff = 0; ff < 16; ff++) {
            const float tt = fast_tanh(kr[ff]);
            t[ff] = tt;
            q[ff] = fmaf(-tt, tt, 1.0f);
        }
        __syncthreads();

        float a[16];
        #pragma unroll
        for (int b = 0; b < 16; b++) a[b] = 1e30f;

        #pragma unroll
        for (int b = 0; b < 16; b++) {
            #pragma unroll
            for (int v = 0; v < 4; v++)
                a[b] = wt_min4(a[b], xs4[(bbase + b) * 16 + fh * 4 + v], t, q, 4 * v);
        }

        // reduce 4 f-chunks -> 1 per b-half
        if (fh >= 2) {
            #pragma unroll
            for (int b = 0; b < 16; b++)
                buf[((bh * 2 + (fh - 2)) * 16 + b) * 128 + c] = a[b];
        }
        __syncthreads();
        if (fh < 2) {
            #pragma unroll
            for (int b = 0; b < 16; b++)
                a[b] = fminf(a[b], buf[((bh * 2 + fh) * 16 + b) * 128 + c]);
        }
        __syncthreads();
        if (fh == 1) {
            #pragma unroll
            for (int b = 0; b < 16; b++)
                buf[((bh * 2) * 16 + b) * 128 + c] = a[b];
        }
        __syncthreads();
        if (fh == 0) {
            float* dst = slot1 ? g_B1 : g_B0;
            #pragma unroll
            for (int b = 0; b < 16; b++) {
                const float r = fminf(a[b], buf[((bh * 2) * 16 + b) * 128 + c]);
                dst[((bbase + b) * KK + m) * CC + c] = r;
            }
        }

    } else if (blk < 144) {
        // ---- unary slots: one (i, slot, b-half16); 8 f-chunks of 16 f ----
        const int  r     = blk - 112;
        const bool slot1 = (r >= 16);
        const int  rr    = r & 15;
        const int  i     = rr >> 1;
        const int  b0    = (rr & 1) * 16;
        const int  tbase = (slot1 ? 192 : 64) + u * 16;

        float kr[16];
        #pragma unroll
        for (int ff = 0; ff < 16; ff++) kr[ff] = kern[(tbase + ff) * CC + c];

        if (tid < 512) {
            const int b = tid >> 5, f4 = tid & 31;
            xs4w[tid] = *reinterpret_cast<const float4*>(
                unary + ((b0 + b) * NN + i) * P1 + f4 * 4);
        }

        float t[16], q[16];
        #pragma unroll
        for (int ff = 0; ff < 16; ff++) {
            const float tt = fast_tanh(kr[ff]);
            t[ff] = tt;
            q[ff] = fmaf(-tt, tt, 1.0f);
        }
        __syncthreads();

        float a[16];
        #pragma unroll
        for (int b = 0; b < 16; b++) a[b] = 1e30f;

        #pragma unroll
        for (int b = 0; b < 16; b++) {
            #pragma unroll
            for (int v = 0; v < 4; v++)
                a[b] = wt_min4(a[b], xs4[b * 32 + u * 4 + v], t, q, 4 * v);
        }

        // reduce 8 f-chunks -> 1
        if (u >= 4) {
            #pragma unroll
            for (int b = 0; b < 16; b++)
                buf[((u - 4) * 16 + b) * 128 + c] = a[b];
        }
        __syncthreads();
        if (u < 4) {
            #pragma unroll
            for (int b = 0; b < 16; b++)
                a[b] = fminf(a[b], buf[(u * 16 + b) * 128 + c]);
        }
        __syncthreads();
        if (u == 2 || u == 3) {
            #pragma unroll
            for (int b = 0; b < 16; b++)
                buf[((u - 2) * 16 + b) * 128 + c] = a[b];
        }
        __syncthreads();
        if (u < 2) {
            #pragma unroll
            for (int b = 0; b < 16; b++)
                a[b] = fminf(a[b], buf[(u * 16 + b) * 128 + c]);
        }
        __syncthreads();
        if (u == 1) {
            #pragma unroll
            for (int b = 0; b < 16; b++)
                buf[b * 128 + c] = a[b];
        }
        __syncthreads();
        if (u == 0) {
            float* dst = slot1 ? g_U1 : g_U0;
            #pragma unroll
            for (int b = 0; b < 16; b++) {
                const float rr2 = fminf(a[b], buf[b * 128 + c]);
                dst[((b0 + b) * NN + i) * CC + c] = rr2;
            }
        }

    } else {
        // ---- nullary slot: 32 b x 64 f; subgroup = (f-chunk 16, b-half 16) ----
        const int fh    = u & 3;
        const int bh    = u >> 2;
        const int bbase = bh * 16;
        const int tbase = fh * 16;

        float kr[16];
        #pragma unroll
        for (int ff = 0; ff < 16; ff++) kr[ff] = kern[(tbase + ff) * CC + c];

        if (tid < 512) {
            const int b = tid >> 4, f4 = tid & 15;
            xs4w[tid] = *reinterpret_cast<const float4*>(nullary + b * P0 + f4 * 4);
        }

        float t[16], q[16];
        #pragma unroll
        for (int ff = 0; ff < 16; ff++) {
            const float tt = fast_tanh(kr[ff]);
            t[ff] = tt;
            q[ff] = fmaf(-tt, tt, 1.0f);
        }
        __syncthreads();

        float a[16];
        #pragma unroll
        for (int b = 0; b < 16; b++) a[b] = 1e30f;

        #pragma unroll
        for (int b = 0; b < 16; b++) {
            #pragma unroll
            for (int v = 0; v < 4; v++)
                a[b] = wt_min4(a[b], xs4[(bbase + b) * 16 + fh * 4 + v], t, q, 4 * v);
        }

        if (fh >= 2) {
            #pragma unroll
            for (int b = 0; b < 16; b++)
                buf[((bh * 2 + (fh - 2)) * 16 + b) * 128 + c] = a[b];
        }
        __syncthreads();
        if (fh < 2) {
            #pragma unroll
            for (int b = 0; b < 16; b++)
                a[b] = fminf(a[b], buf[((bh * 2 + fh) * 16 + b) * 128 + c]);
        }
        __syncthreads();
        if (fh == 1) {
            #pragma unroll
            for (int b = 0; b < 16; b++)
                buf[((bh * 2) * 16 + b) * 128 + c] = a[b];
        }
        __syncthreads();
        if (fh == 0) {
            #pragma unroll
            for (int b = 0; b < 16; b++) {
                const float r = fminf(a[b], buf[((bh * 2) * 16 + b) * 128 + c]);
                g_N0[(bbase + b) * CC + c] = r;
            }
        }
    }

    // ================= Grid soft-barrier (distributed, 8 padded counters) =========
    __threadfence();
    __syncthreads();
    if (tid == 0) atomicAdd(&g_arr[(blk & 7) << 5], 1);

    if (blk >= PB) return;   // only blocks 0..31 combine

    // 145 blocks: residue 0 gets 19 arrivals (blk 0,8,...,144), residues 1..7 get 18.
    if (tid < 8) {
        const int target = 18 + (tid == 0 ? 1 : 0);
        while (*((volatile int*)&g_arr[tid << 5]) < target) { }
    }
    __syncthreads();
    __threadfence();

    // ================= Phase 2: combine for batch b = blk =================
    {
        const int b = blk;
        const int k0 = u * 7;   // subgroup handles k in [u*7, u*7+7)

        // Batch all loads first (29 LDGs, high MLP)
        float bv0[7], bv1[7], uu[7];
        #pragma unroll
        for (int kk = 0; kk < 7; kk++) {
            const int k  = k0 + kk;
            const int i  = k / 7;
            const int r  = k % 7;
            const int j  = r + (r >= i);
            const int rv = j * 7 + (i - (i > j));  // reversed-pair index
            bv0[kk] = g_B0[(b * KK + k)  * CC + c];
            bv1[kk] = g_B1[(b * KK + rv) * CC + c];
            uu[kk]  = fminf(g_U0[(b * NN + i) * CC + c],
                            g_U1[(b * NN + j) * CC + c]);
        }
        const float n0 = g_N0[b * CC + c];

        float mx = -1e30f;
        #pragma unroll
        for (int kk = 0; kk < 7; kk++) {
            const float v = fminf(fminf(bv0[kk], bv1[kk]), fminf(uu[kk], n0));
            mx = fmaxf(mx, v);
        }
        buf[u * CC + c] = mx;
        __syncthreads();
        if (tid < CC) {
            float m01 = fmaxf(buf[c],            buf[1 * CC + c]);
            float m23 = fmaxf(buf[2 * CC + c],   buf[3 * CC + c]);
            float m45 = fmaxf(buf[4 * CC + c],   buf[5 * CC + c]);
            float m67 = fmaxf(buf[6 * CC + c],   buf[7 * CC + c]);
            out[b * CC + c] = fmaxf(fmaxf(m01, m23), fmaxf(m45, m67));
        }
    }

    // ================= Counter reset for graph replay =================
    // Safe: every combine block has passed the poll (which required all 145
    // arrivals) before incrementing g_done, so the reset by the last finisher
    // cannot race any poller or arriver of this launch.
    __syncthreads();
    if (tid == 0) {
        const int old = atomicAdd(&g_done, 1);
        if (old == PB - 1) {
            #pragma unroll
            for (int s = 0; s < 8; s++) atomicExch(&g_arr[s << 5], 0);
            atomicExch(&g_done, 0);
        }
    }
}

extern "C" void kernel_launch(void* const* d_in, const int* in_sizes, int n_in,
                              void* d_out, int out_size) {
    const float* nullary = (const float*)d_in[0];  // (32, 64)
    const float* unary   = (const float*)d_in[1];  // (32, 8, 128)
    const float* binary  = (const float*)d_in[2];  // (32, 8, 7, 64)
    const float* kern    = (const float*)d_in[3];  // (448, 128)
    float* out = (float*)d_out;                    // (32, 128)

    fused_k<<<GRID, NT>>>(nullary, unary, binary, kern, out);
}

// round 16
// speedup vs baseline: 2.7674x; 1.1034x over previous
#include <cuda_runtime.h>
#include <cuda_bf16.h>

// Problem constants
#define PB    32    // batch
#define NN    8     // objects
#define P0    64
#define P1    128
#define P2    64
#define CC    128   // channels
#define KK    56    // permutations of (8,2)
#define NT    1024  // threads: 8 subgroups x 128 channels
#define GRID  145   // 112 binary + 32 unary + 1 nullary (single wave on 148 SMs)

// Scratch (allocation-free: __device__ globals)
__device__ float g_N0[PB * CC];
__device__ float g_U0[PB * NN * CC];
__device__ float g_U1[PB * NN * CC];
__device__ float g_B0[PB * KK * CC];
__device__ float g_B1[PB * KK * CC];
// 8 arrive counters, each on its own 128B line (stride 32 ints).
__device__ int   g_arr[8 * 32];
__device__ int   g_done;

// HW tanh: single MUFU op on sm_75+ (abs err ~1e-4, inside the 1e-3 gate).
__device__ __forceinline__ float tanh_hw(float x) {
    float r;
    asm("tanh.approx.f32 %0, %1;" : "=f"(r) : "f"(x));
    return r;
}

// 4 weighted-truth FMAs as 2 packed fma.rn.f32x2 + tree min, folded into acc.
// Per-lane math is identical IEEE fma; packs/unpacks ride even register pairs.
__device__ __forceinline__ float wt_min4(float acc, float4 xv,
                                         const unsigned long long* t2,
                                         const unsigned long long* q2, int p) {
    unsigned long long x01, x23, w01, w23;
    asm("mov.b64 %0, {%1, %2};" : "=l"(x01) : "f"(xv.x), "f"(xv.y));
    asm("mov.b64 %0, {%1, %2};" : "=l"(x23) : "f"(xv.z), "f"(xv.w));
    asm("fma.rn.f32x2 %0, %1, %2, %3;" : "=l"(w01) : "l"(x01), "l"(t2[p]),     "l"(q2[p]));
    asm("fma.rn.f32x2 %0, %1, %2, %3;" : "=l"(w23) : "l"(x23), "l"(t2[p + 1]), "l"(q2[p + 1]));
    float w0, w1, w2, w3;
    asm("mov.b64 {%0, %1}, %2;" : "=f"(w0), "=f"(w1) : "l"(w01));
    asm("mov.b64 {%0, %1}, %2;" : "=f"(w2), "=f"(w3) : "l"(w23));
    return fminf(acc, fminf(fminf(w0, w1), fminf(w2, w3)));
}

// Compute 16 (t, q) pairs from kr[16] into packed f32x2 registers.
__device__ __forceinline__ void make_tq(const float* kr,
                                        unsigned long long* t2,
                                        unsigned long long* q2) {
    #pragma unroll
    for (int p = 0; p < 8; p++) {
        const float ta = tanh_hw(kr[2 * p]);
        const float tb = tanh_hw(kr[2 * p + 1]);
        const float qa = fmaf(-ta, ta, 1.0f);
        const float qb = fmaf(-tb, tb, 1.0f);
        asm("mov.b64 %0, {%1, %2};" : "=l"(t2[p]) : "f"(ta), "f"(tb));
        asm("mov.b64 %0, {%1, %2};" : "=l"(q2[p]) : "f"(qa), "f"(qb));
    }
}

__global__ __launch_bounds__(NT) void fused_k(const float* __restrict__ nullary,
                                              const float* __restrict__ unary,
                                              const float* __restrict__ binary,
                                              const float* __restrict__ kern,
                                              float* __restrict__ out) {
    __shared__ __align__(16) float xs[2048];   // 8 KB  x staging (b-major)
    __shared__ __align__(16) float buf[8192];  // 32 KB reduction buffer

    const int blk = blockIdx.x;
    const int tid = threadIdx.x;
    const int u   = tid >> 7;     // subgroup 0..7
    const int c   = tid & 127;    // channel
    const float4* xs4 = reinterpret_cast<const float4*>(xs);
    float4* xs4w = reinterpret_cast<float4*>(xs);

    // ================= Phase 1: slot-partial mins =================
    if (blk < 112) {
        // ---- binary slots: one pair m; subgroup = (f-chunk 16, b-half 16) ----
        const bool slot1 = (blk >= 56);
        const int  m     = slot1 ? blk - 56 : blk;
        const int  i     = m / 7;
        const int  jp    = m % 7;
        const int  fh    = u & 3;           // f-chunk 0..3 (16 f each)
        const int  bh    = u >> 2;          // b-half 0..1 (16 b each)
        const int  bbase = bh * 16;
        const int  tbase = (slot1 ? 384 : 320) + fh * 16;

        // 1) kern loads issued first (latency covered by staging below)
        float kr[16];
        #pragma unroll
        for (int ff = 0; ff < 16; ff++) kr[ff] = kern[(tbase + ff) * CC + c];

        // 2) x staging: 512 float4
        if (tid < 512) {
            const int b = tid >> 4, f4 = tid & 15;
            xs4w[tid] = *reinterpret_cast<const float4*>(
                binary + ((b * NN + i) * (NN - 1) + jp) * P2 + f4 * 4);
        }

        // 3) tanh -> packed (t, q)
        unsigned long long t2[8], q2[8];
        make_tq(kr, t2, q2);
        __syncthreads();

        float a[16];
        #pragma unroll
        for (int b = 0; b < 16; b++) a[b] = 1e30f;

        #pragma unroll
        for (int b = 0; b < 16; b++) {
            #pragma unroll
            for (int v = 0; v < 4; v++)
                a[b] = wt_min4(a[b], xs4[(bbase + b) * 16 + fh * 4 + v], t2, q2, 2 * v);
        }

        // reduce 4 f-chunks -> 1 per b-half
        if (fh >= 2) {
            #pragma unroll
            for (int b = 0; b < 16; b++)
                buf[((bh * 2 + (fh - 2)) * 16 + b) * 128 + c] = a[b];
        }
        __syncthreads();
        if (fh < 2) {
            #pragma unroll
            for (int b = 0; b < 16; b++)
                a[b] = fminf(a[b], buf[((bh * 2 + fh) * 16 + b) * 128 + c]);
        }
        __syncthreads();
        if (fh == 1) {
            #pragma unroll
            for (int b = 0; b < 16; b++)
                buf[((bh * 2) * 16 + b) * 128 + c] = a[b];
        }
        __syncthreads();
        if (fh == 0) {
            float* dst = slot1 ? g_B1 : g_B0;
            #pragma unroll
            for (int b = 0; b < 16; b++) {
                const float r = fminf(a[b], buf[((bh * 2) * 16 + b) * 128 + c]);
                dst[((bbase + b) * KK + m) * CC + c] = r;
            }
        }

    } else if (blk < 144) {
        // ---- unary slots: one (i, slot, b-half16); 8 f-chunks of 16 f ----
        const int  r     = blk - 112;
        const bool slot1 = (r >= 16);
        const int  rr    = r & 15;
        const int  i     = rr >> 1;
        const int  b0    = (rr & 1) * 16;
        const int  tbase = (slot1 ? 192 : 64) + u * 16;

        float kr[16];
        #pragma unroll
        for (int ff = 0; ff < 16; ff++) kr[ff] = kern[(tbase + ff) * CC + c];

        if (tid < 512) {
            const int b = tid >> 5, f4 = tid & 31;
            xs4w[tid] = *reinterpret_cast<const float4*>(
                unary + ((b0 + b) * NN + i) * P1 + f4 * 4);
        }

        unsigned long long t2[8], q2[8];
        make_tq(kr, t2, q2);
        __syncthreads();

        float a[16];
        #pragma unroll
        for (int b = 0; b < 16; b++) a[b] = 1e30f;

        #pragma unroll
        for (int b = 0; b < 16; b++) {
            #pragma unroll
            for (int v = 0; v < 4; v++)
                a[b] = wt_min4(a[b], xs4[b * 32 + u * 4 + v], t2, q2, 2 * v);
        }

        // reduce 8 f-chunks -> 1
        if (u >= 4) {
            #pragma unroll
            for (int b = 0; b < 16; b++)
                buf[((u - 4) * 16 + b) * 128 + c] = a[b];
        }
        __syncthreads();
        if (u < 4) {
            #pragma unroll
            for (int b = 0; b < 16; b++)
                a[b] = fminf(a[b], buf[(u * 16 + b) * 128 + c]);
        }
        __syncthreads();
        if (u == 2 || u == 3) {
            #pragma unroll
            for (int b = 0; b < 16; b++)
                buf[((u - 2) * 16 + b) * 128 + c] = a[b];
        }
        __syncthreads();
        if (u < 2) {
            #pragma unroll
            for (int b = 0; b < 16; b++)
                a[b] = fminf(a[b], buf[(u * 16 + b) * 128 + c]);
        }
        __syncthreads();
        if (u == 1) {
            #pragma unroll
            for (int b = 0; b < 16; b++)
                buf[b * 128 + c] = a[b];
        }
        __syncthreads();
        if (u == 0) {
            float* dst = slot1 ? g_U1 : g_U0;
            #pragma unroll
            for (int b = 0; b < 16; b++) {
                const float rr2 = fminf(a[b], buf[b * 128 + c]);
                dst[((b0 + b) * NN + i) * CC + c] = rr2;
            }
        }

    } else {
        // ---- nullary slot: 32 b x 64 f; subgroup = (f-chunk 16, b-half 16) ----
        const int fh    = u & 3;
        const int bh    = u >> 2;
        const int bbase = bh * 16;
        const int tbase = fh * 16;

        float kr[16];
        #pragma unroll
        for (int ff = 0; ff < 16; ff++) kr[ff] = kern[(tbase + ff) * CC + c];

        if (tid < 512) {
            const int b = tid >> 4, f4 = tid & 15;
            xs4w[tid] = *reinterpret_cast<const float4*>(nullary + b * P0 + f4 * 4);
        }

        unsigned long long t2[8], q2[8];
        make_tq(kr, t2, q2);
        __syncthreads();

        float a[16];
        #pragma unroll
        for (int b = 0; b < 16; b++) a[b] = 1e30f;

        #pragma unroll
        for (int b = 0; b < 16; b++) {
            #pragma unroll
            for (int v = 0; v < 4; v++)
                a[b] = wt_min4(a[b], xs4[(bbase + b) * 16 + fh * 4 + v], t2, q2, 2 * v);
        }

        if (fh >= 2) {
            #pragma unroll
            for (int b = 0; b < 16; b++)
                buf[((bh * 2 + (fh - 2)) * 16 + b) * 128 + c] = a[b];
        }
        __syncthreads();
        if (fh < 2) {
            #pragma unroll
            for (int b = 0; b < 16; b++)
                a[b] = fminf(a[b], buf[((bh * 2 + fh) * 16 + b) * 128 + c]);
        }
        __syncthreads();
        if (fh == 1) {
            #pragma unroll
            for (int b = 0; b < 16; b++)
                buf[((bh * 2) * 16 + b) * 128 + c] = a[b];
        }
        __syncthreads();
        if (fh == 0) {
            #pragma unroll
            for (int b = 0; b < 16; b++) {
                const float r = fminf(a[b], buf[((bh * 2) * 16 + b) * 128 + c]);
                g_N0[(bbase + b) * CC + c] = r;
            }
        }
    }

    // ================= Grid soft-barrier (distributed, 8 padded counters) =========
    __threadfence();
    __syncthreads();
    if (tid == 0) atomicAdd(&g_arr[(blk & 7) << 5], 1);

    if (blk >= PB) return;   // only blocks 0..31 combine

    // 145 blocks: residue 0 gets 19 arrivals (blk 0,8,...,144), residues 1..7 get 18.
    if (tid < 8) {
        const int target = 18 + (tid == 0 ? 1 : 0);
        while (*((volatile int*)&g_arr[tid << 5]) < target) { }
    }
    __syncthreads();
    __threadfence();

    // ================= Phase 2: combine for batch b = blk =================
    {
        const int b = blk;
        const int k0 = u * 7;   // subgroup handles k in [u*7, u*7+7)

        float bv0[7], bv1[7], uu[7];
        #pragma unroll
        for (int kk = 0; kk < 7; kk++) {
            const int k  = k0 + kk;
            const int i  = k / 7;
            const int r  = k % 7;
            const int j  = r + (r >= i);
            const int rv = j * 7 + (i - (i > j));  // reversed-pair index
            bv0[kk] = g_B0[(b * KK + k)  * CC + c];
            bv1[kk] = g_B1[(b * KK + rv) * CC + c];
            uu[kk]  = fminf(g_U0[(b * NN + i) * CC + c],
                            g_U1[(b * NN + j) * CC + c]);
        }
        const float n0 = g_N0[b * CC + c];

        float mx = -1e30f;
        #pragma unroll
        for (int kk = 0; kk < 7; kk++) {
            const float v = fminf(fminf(bv0[kk], bv1[kk]), fminf(uu[kk], n0));
            mx = fmaxf(mx, v);
        }
        buf[u * CC + c] = mx;
        __syncthreads();
        if (tid < CC) {
            float m01 = fmaxf(buf[c],            buf[1 * CC + c]);
            float m23 = fmaxf(buf[2 * CC + c],   buf[3 * CC + c]);
            float m45 = fmaxf(buf[4 * CC + c],   buf[5 * CC + c]);
            float m67 = fmaxf(buf[6 * CC + c],   buf[7 * CC + c]);
            out[b * CC + c] = fmaxf(fmaxf(m01, m23), fmaxf(m45, m67));
        }
    }

    // ================= Counter reset for graph replay =================
    __syncthreads();
    if (tid == 0) {
        const int old = atomicAdd(&g_done, 1);
        if (old == PB - 1) {
            #pragma unroll
            for (int s = 0; s < 8; s++) atomicExch(&g_arr[s << 5], 0);
            atomicExch(&g_done, 0);
        }
    }
}

extern "C" void kernel_launch(void* const* d_in, const int* in_sizes, int n_in,
                              void* d_out, int out_size) {
    const float* nullary = (const float*)d_in[0];  // (32, 64)
    const float* unary   = (const float*)d_in[1];  // (32, 8, 128)
    const float* binary  = (const float*)d_in[2];  // (32, 8, 7, 64)
    const float* kern    = (const float*)d_in[3];  // (448, 128)
    float* out = (float*)d_out;                    // (32, 128)

    fused_k<<<GRID, NT>>>(nullary, unary, binary, kern, out);
}